// round 2
// baseline (speedup 1.0000x reference)
#include <cuda_runtime.h>
#include <float.h>
#include <math.h>

#define BB 8
#define DD 256
#define MEMN 131072
#define CWN 64
#define RR 4
#define KK 4
#define TKL 8
#define CC 25
#define DELTA_F 0.005f
#define EPS_F 1e-6f

#define NBLK 64
#define ROWS_PER_BLK (MEMN / NBLK)   // 2048
#define UMB 16
#define UMCH (MEMN / UMB)            // 8192

// ---------------- device scratch (no allocations allowed) ----------------
__device__ float g_q[BB][DD];                 // raw read_query
__device__ float g_visnew[BB][CC][CWN];       // updated visible_memory rows
__device__ float g_relnew[BB][CC];            // updated usage at read positions
__device__ int   g_fp[BB][KK];
__device__ int   g_bp[BB][KK];
__device__ float g_bv[BB][RR][NBLK][KK];      // per-block top-4 values
__device__ int   g_bi[BB][RR][NBLK][KK];      // per-block top-4 indices
__device__ float g_uv[UMB];                   // usage argmin partials (batch 0)
__device__ int   g_ui[UMB];

// ---------------- helpers ----------------
__device__ __forceinline__ float d4(float4 a, float4 b, float acc) {
    acc = fmaf(a.x, b.x, acc);
    acc = fmaf(a.y, b.y, acc);
    acc = fmaf(a.z, b.z, acc);
    acc = fmaf(a.w, b.w, acc);
    return acc;
}

// top-4 insertion; larger value wins, ties -> lower index (jax.lax.top_k)
__device__ __forceinline__ void ins4s(float s, int m,
    float &v0, int &i0, float &v1, int &i1,
    float &v2, int &i2, float &v3, int &i3)
{
    if (!((s > v3) || (s == v3 && m < i3))) return;
    v3 = s; i3 = m;
    if ((v3 > v2) || (v3 == v2 && i3 < i2)) { float tv=v2; int ti=i2; v2=v3; i2=i3; v3=tv; i3=ti; }
    if ((v2 > v1) || (v2 == v1 && i2 < i1)) { float tv=v1; int ti=i1; v1=v2; i1=i2; v2=tv; i2=ti; }
    if ((v1 > v0) || (v1 == v0 && i1 < i0)) { float tv=v0; int ti=i0; v0=v1; i0=i1; v1=tv; i1=ti; }
}

__device__ __forceinline__ float sig_(float x) { return 1.f / (1.f + expf(-x)); }

// ============================================================================
// K1: projections + small state updates + link diagonals + fp/bp. 1 block/batch
// ============================================================================
__global__ void __launch_bounds__(256) k1_setup(
    const float* __restrict__ xi,
    const float* __restrict__ visible_memory,
    const float* __restrict__ link_matrix,
    const float* __restrict__ rev_link_matrix,
    const float* __restrict__ precedence,
    const float* __restrict__ read_weights,
    const float* __restrict__ write_weights,
    const float* __restrict__ usage,
    const int*   __restrict__ read_positions,
    const float* __restrict__ W_rq, const float* __restrict__ b_rq,
    const float* __restrict__ W_wv, const float* __restrict__ b_wv,
    const float* __restrict__ W_ig, const float* __restrict__ b_ig,
    const float* __restrict__ W_wg, const float* __restrict__ b_wg)
{
    int b = blockIdx.x;
    int t = threadIdx.x;

    __shared__ float xs[DD];
    __shared__ float wv_s[CWN];
    __shared__ float ig_s[CC];
    __shared__ float wg_s;
    __shared__ int   rp_s[CC];
    __shared__ float rw_s[CC], rel_s[CC], u_s[CC], imin_s[CC], wwnew_s[CC];
    __shared__ float minrel_s;

    xs[t] = xi[b * DD + t];
    __syncthreads();

    // read_query: 256 outputs
    {
        float acc = b_rq[t];
        for (int d = 0; d < DD; d++) acc = fmaf(xs[d], W_rq[d * 256 + t], acc);
        g_q[b][t] = acc;
    }
    if (t < CWN) {
        float acc = b_wv[t];
        for (int d = 0; d < DD; d++) acc = fmaf(xs[d], W_wv[d * CWN + t], acc);
        wv_s[t] = acc;
    }
    if (t < CC) {
        float acc = b_ig[t];
        for (int d = 0; d < DD; d++) acc = fmaf(xs[d], W_ig[d * CC + t], acc);
        ig_s[t] = sig_(acc);
        rp_s[t] = read_positions[b * CC + t];
    }
    if (t == 0) {
        float acc = b_wg[0];
        for (int d = 0; d < DD; d++) acc = fmaf(xs[d], W_wg[d], acc);
        wg_s = sig_(acc);
    }
    __syncthreads();

    if (t < CC) {
        int p = rp_s[t];
        float rw  = read_weights [(size_t)b * MEMN + p];
        float ww  = write_weights[(size_t)b * MEMN + p];
        float rel = usage        [(size_t)b * MEMN + p];
        rw_s[t]  = rw;
        rel_s[t] = rel;
        u_s[t]   = (rw + ww > DELTA_F) ? 1.f : 0.f;
    }
    __syncthreads();
    if (t == 0) {
        float mn = rel_s[0];
        for (int c = 1; c < CC; c++) mn = fminf(mn, rel_s[c]);
        minrel_s = mn;
    }
    __syncthreads();
    if (t < CC) {
        float Imin = (rel_s[t] == minrel_s) ? 1.f : 0.f;
        imin_s[t] = Imin;
        float u = u_s[t], rel = rel_s[t];
        g_relnew[b][t] = (1.f - rel) * u + rel * (1.f - u);   // TIMESTEP = 1
        wwnew_s[t] = wg_s * (ig_s[t] * rw_s[t] + (1.f - ig_s[t]) * Imin);
    }
    __syncthreads();

    // updated visible_memory rows
    for (int e = t; e < CC * CWN; e += blockDim.x) {
        int c = e / CWN, k = e % CWN;
        float v = visible_memory[((size_t)b * CC + c) * CWN + k];
        g_visnew[b][c][k] = v * (1.f - imin_s[c]) + wwnew_s[c] * wv_s[k];
    }

    // link / rev-link diagonals (Ieye zeros everything else) -> fp / bp
    if (t == 0) {
        float fwdw[TKL], bwdw[TKL];
        for (int m = 0; m < TKL; m++) {
            // updated write_weights at index m (scatter, last writer wins)
            float wwf = write_weights[(size_t)b * MEMN + m];
            for (int c = 0; c < CC; c++) if (rp_s[c] == m) wwf = wwnew_s[c];
            // tww[m] = updated write_weights at trp[m] = rp[16+m]
            int tp = rp_s[RR * KK + m];
            float tw = write_weights[(size_t)b * MEMN + tp];
            for (int c = 0; c < CC; c++) if (rp_s[c] == tp) tw = wwnew_s[c];
            // prec_dense[m] : precedence scattered at trp, read at m (last j wins)
            float pd = 0.f;
            for (int j = 0; j < TKL; j++)
                if (rp_s[RR * KK + j] == m) pd = precedence[b * TKL + j];
            float trw = read_weights[(size_t)b * MEMN + tp];
            float Ld = (1.f - wwf) * link_matrix    [((size_t)b * MEMN + m) * TKL + m]
                     + wwf * precedence[b * TKL + m];
            float Rd = (1.f - tw ) * rev_link_matrix[((size_t)b * MEMN + m) * TKL + m]
                     + tw  * pd;
            fwdw[m] = Ld * trw;
            bwdw[m] = Rd * trw;
        }
        bool used[TKL];
        for (int m = 0; m < TKL; m++) used[m] = false;
        for (int k = 0; k < KK; k++) {
            int best = -1;
            for (int m = 0; m < TKL; m++)
                if (!used[m] && (best < 0 || fwdw[m] > fwdw[best])) best = m;
            used[best] = true;
            g_fp[b][k] = best;
        }
        for (int m = 0; m < TKL; m++) used[m] = false;
        for (int k = 0; k < KK; k++) {
            int best = -1;
            for (int m = 0; m < TKL; m++)
                if (!used[m] && (best < 0 || bwdw[m] > bwdw[best])) best = m;
            used[best] = true;
            g_bp[b][k] = best;
        }
    }
}

// ============================================================================
// K2: full-memory score scan (coalesced, 8 lanes/row) + per-block top-4.
//     Extra UMB blocks: masked usage argmin for batch 0.
// ============================================================================
__global__ void __launch_bounds__(256) k2_scan(
    const float* __restrict__ memv,
    const float* __restrict__ usage,
    const int*   __restrict__ rp)
{
    int t = threadIdx.x;

    if (blockIdx.x >= BB * NBLK) {
        // ---- usage argmin for batch 0 (read positions masked out) ----
        int ib = blockIdx.x - BB * NBLK;
        __shared__ int   rp0[CC];
        __shared__ float svv[256];
        __shared__ int   sii[256];
        if (t < CC) rp0[t] = rp[t];
        __syncthreads();
        float bv = FLT_MAX; int bi = 0x7fffffff;
        int base = ib * UMCH;
        for (int j = t; j < UMCH; j += 256) {
            int idx = base + j;
            float v = usage[idx];
            bool masked = false;
            #pragma unroll
            for (int c = 0; c < CC; c++) masked |= (rp0[c] == idx);
            if (!masked && (v < bv || (v == bv && idx < bi))) { bv = v; bi = idx; }
        }
        svv[t] = bv; sii[t] = bi;
        __syncthreads();
        for (int s = 128; s > 0; s >>= 1) {
            if (t < s) {
                if (svv[t+s] < svv[t] || (svv[t+s] == svv[t] && sii[t+s] < sii[t])) {
                    svv[t] = svv[t+s]; sii[t] = sii[t+s];
                }
            }
            __syncthreads();
        }
        if (t == 0) { g_uv[ib] = svv[0]; g_ui[ib] = sii[0]; }
        return;
    }

    int b   = blockIdx.x / NBLK;
    int blk = blockIdx.x % NBLK;
    int rowbase = blk * ROWS_PER_BLK;
    int lane = t & 31, w = t >> 5;
    int sub = lane & 7, grp = lane >> 3;

    __shared__ int ns;
    __shared__ int srow[CC];
    __shared__ float msv[RR][128];
    __shared__ int   msi[RR][128];
    if (t == 0) ns = 0;
    __syncthreads();
    if (t < CC) {
        int p = rp[b * CC + t];
        if (p >= rowbase && p < rowbase + ROWS_PER_BLK) { int k = atomicAdd(&ns, 1); srow[k] = p; }
    }

    // query columns for this lane: cols sub*4..+3 and 32+sub*4..+3, all 4 queries
    float4 q0[RR], q1[RR];
    #pragma unroll
    for (int r = 0; r < RR; r++) {
        q0[r] = *(const float4*)&g_q[b][r * CWN + sub * 4];
        q1[r] = *(const float4*)&g_q[b][r * CWN + 32 + sub * 4];
    }
    __syncthreads();
    int nspec = ns;

    float tv0 = -FLT_MAX, tv1 = -FLT_MAX, tv2 = -FLT_MAX, tv3 = -FLT_MAX;
    int   ti0 = 0x7fffffff, ti1 = 0x7fffffff, ti2 = 0x7fffffff, ti3 = 0x7fffffff;

    const float4* basep = (const float4*)(memv + (size_t)b * MEMN * CWN);
    #pragma unroll 2
    for (int it = 0; it < ROWS_PER_BLK / 32; it++) {
        int row = rowbase + it * 32 + w * 4 + grp;
        const float4* p = basep + (size_t)row * 16;
        float4 a0 = p[sub];
        float4 a1 = p[8 + sub];

        float sq = d4(a0, a0, 0.f); sq = d4(a1, a1, sq);
        float dt0 = d4(a0, q0[0], 0.f); dt0 = d4(a1, q1[0], dt0);
        float dt1 = d4(a0, q0[1], 0.f); dt1 = d4(a1, q1[1], dt1);
        float dt2 = d4(a0, q0[2], 0.f); dt2 = d4(a1, q1[2], dt2);
        float dt3 = d4(a0, q0[3], 0.f); dt3 = d4(a1, q1[3], dt3);

        #pragma unroll
        for (int m = 4; m >= 1; m >>= 1) {
            sq  += __shfl_xor_sync(0xffffffffu, sq,  m);
            dt0 += __shfl_xor_sync(0xffffffffu, dt0, m);
            dt1 += __shfl_xor_sync(0xffffffffu, dt1, m);
            dt2 += __shfl_xor_sync(0xffffffffu, dt2, m);
            dt3 += __shfl_xor_sync(0xffffffffu, dt3, m);
        }

        if (sub < RR) {
            float myd = (sub == 0) ? dt0 : (sub == 1) ? dt1 : (sub == 2) ? dt2 : dt3;
            float s = 2.f * myd - sq;
            for (int j = 0; j < nspec; j++) if (srow[j] == row) s = -FLT_MAX;
            ins4s(s, row, tv0, ti0, tv1, ti1, tv2, ti2, tv3, ti3);
        }
    }

    if (sub < RR) {
        int slot = w * 16 + grp * 4;
        msv[sub][slot + 0] = tv0; msi[sub][slot + 0] = ti0;
        msv[sub][slot + 1] = tv1; msi[sub][slot + 1] = ti1;
        msv[sub][slot + 2] = tv2; msi[sub][slot + 2] = ti2;
        msv[sub][slot + 3] = tv3; msi[sub][slot + 3] = ti3;
    }
    __syncthreads();

    if (t < RR) {
        float v0 = -FLT_MAX, v1 = -FLT_MAX, v2 = -FLT_MAX, v3 = -FLT_MAX;
        int   i0 = 0x7fffffff, i1 = 0x7fffffff, i2 = 0x7fffffff, i3 = 0x7fffffff;
        for (int j = 0; j < 128; j++)
            ins4s(msv[t][j], msi[t][j], v0, i0, v1, i1, v2, i2, v3, i3);
        g_bv[b][t][blk][0] = v0; g_bi[b][t][blk][0] = i0;
        g_bv[b][t][blk][1] = v1; g_bi[b][t][blk][1] = i1;
        g_bv[b][t][blk][2] = v2; g_bi[b][t][blk][2] = i2;
        g_bv[b][t][blk][3] = v3; g_bi[b][t][blk][3] = i3;
    }
}

// ============================================================================
// K3: global merge + fp/bp/lum + clip + gather(with substitution) + cosine
//     softmax read. 1 block/batch.
// ============================================================================
__global__ void __launch_bounds__(256) k3_finish(
    const float* __restrict__ memv,
    const int*   __restrict__ rp,
    float* __restrict__ out)
{
    int b = blockIdx.x;
    int t = threadIdx.x;

    __shared__ float q[RR][CWN];
    __shared__ float kq[RR][CWN];
    __shared__ float qn[RR];
    __shared__ int   rps[CC];
    __shared__ int   valid[CC];
    __shared__ float specs[RR][CC];
    __shared__ float cv[RR][NBLK * KK];
    __shared__ int   ci[RR][NBLK * KK];
    __shared__ int   pos[CC];
    __shared__ int   maxlen_s;
    __shared__ int   rowsrc[CC];
    __shared__ float vis[CC][CWN];
    __shared__ float vinv[CC];
    __shared__ float sim[RR][CC];
    __shared__ float sw[RR][CC];

    // 1. load q
    q[t >> 6][t & 63] = g_q[b][t];
    __syncthreads();

    // 2. q norms, read positions, stage block candidates
    if (t < RR) {
        float s = 0.f;
        for (int wc = 0; wc < CWN; wc++) s = fmaf(q[t][wc], q[t][wc], s);
        qn[t] = 1.f / (sqrtf(s) + EPS_F);
    }
    if (t >= 32 && t < 32 + CC) rps[t - 32] = rp[b * CC + (t - 32)];
    for (int e = t; e < RR * NBLK * KK; e += 256) {
        int r = e / (NBLK * KK), j = e % (NBLK * KK);
        cv[r][j] = (&g_bv[b][r][0][0])[j];
        ci[r][j] = (&g_bi[b][r][0][0])[j];
    }
    __syncthreads();

    // 3. kq, validity (last occurrence), special-row scores, max_length
    kq[t >> 6][t & 63] = q[t >> 6][t & 63] * qn[t >> 6];
    if (t < CC) {
        int v = 1;
        for (int c = t + 1; c < CC; c++) if (rps[c] == rps[t]) v = 0;
        valid[t] = v;
    }
    if (t >= 128 && t < 128 + RR * CC) {
        int e = t - 128;
        int c = e / RR, r = e % RR;
        float dt = 0.f, sq = 0.f;
        for (int wc = 0; wc < CWN; wc++) {
            float m = g_visnew[b][c][wc];
            dt = fmaf(q[r][wc], m, dt);
            sq = fmaf(m, m, sq);
        }
        specs[r][c] = 2.f * dt - sq;
    }
    if (t == 255) {
        float bv = FLT_MAX; int bi = 0x7fffffff;
        for (int i = 0; i < UMB; i++) {
            float v = g_uv[i]; int ix = g_ui[i];
            if (v < bv || (v == bv && ix < bi)) { bv = v; bi = ix; }
        }
        for (int c = 0; c < CC; c++) {
            int p0 = rp[c];                 // batch 0
            int last = 1;
            for (int c2 = c + 1; c2 < CC; c2++) if (rp[c2] == p0) last = 0;
            if (!last) continue;
            float v = g_relnew[0][c];
            if (v < bv || (v == bv && p0 < bi)) { bv = v; bi = p0; }
        }
        maxlen_s = bi;
    }
    __syncthreads();

    // 4. global top-4 per r; assemble positions
    if (t < RR) {
        float v0 = -FLT_MAX, v1 = -FLT_MAX, v2 = -FLT_MAX, v3 = -FLT_MAX;
        int   i0 = 0x7fffffff, i1 = 0x7fffffff, i2 = 0x7fffffff, i3 = 0x7fffffff;
        for (int j = 0; j < NBLK * KK; j++)
            ins4s(cv[t][j], ci[t][j], v0, i0, v1, i1, v2, i2, v3, i3);
        for (int c = 0; c < CC; c++)
            if (valid[c]) ins4s(specs[t][c], rps[c], v0, i0, v1, i1, v2, i2, v3, i3);
        pos[t * 4 + 0] = i0; pos[t * 4 + 1] = i1; pos[t * 4 + 2] = i2; pos[t * 4 + 3] = i3;
    }
    if (t == 4) {
        for (int k = 0; k < KK; k++) { pos[16 + k] = g_fp[b][k]; pos[20 + k] = g_bp[b][k]; }
        pos[24] = CC + 1;   // lum = C + 1 = 26
    }
    __syncthreads();

    // 5. clip + row source (substitute updated rows; last occurrence wins)
    if (t < CC) {
        int p = pos[t];
        int ml = maxlen_s;
        p = p < 0 ? 0 : (p > ml ? ml : p);
        pos[t] = p;
        int s = -1;
        for (int c = 0; c < CC; c++) if (rps[c] == p) s = c;
        rowsrc[t] = s;
    }
    __syncthreads();

    // 6. gather visible rows
    for (int e = t; e < CC * CWN; e += 256) {
        int c = e / CWN, wc = e % CWN;
        int s = rowsrc[c];
        vis[c][wc] = (s >= 0) ? g_visnew[b][s][wc]
                              : memv[((size_t)b * MEMN + pos[c]) * CWN + wc];
    }
    __syncthreads();

    // 7. visible norms
    if (t < CC) {
        float s = 0.f;
        for (int wc = 0; wc < CWN; wc++) s = fmaf(vis[t][wc], vis[t][wc], s);
        vinv[t] = 1.f / (sqrtf(s) + EPS_F);
    }
    __syncthreads();

    // 8. cosine similarities
    if (t < RR * CC) {
        int r = t / CC, c = t % CC;
        float s = 0.f;
        for (int wc = 0; wc < CWN; wc++) s = fmaf(kq[r][wc], vis[c][wc], s);
        sim[r][c] = s * vinv[c];
    }
    __syncthreads();

    // 9. softmax over candidates
    if (t < RR) {
        float mx = -FLT_MAX;
        for (int c = 0; c < CC; c++) mx = fmaxf(mx, sim[t][c]);
        float sum = 0.f;
        for (int c = 0; c < CC; c++) { float e = expf(sim[t][c] - mx); sw[t][c] = e; sum += e; }
        float inv = 1.f / sum;
        for (int c = 0; c < CC; c++) sw[t][c] *= inv;
    }
    __syncthreads();

    // 10. read vectors
    {
        int r = t >> 6, wc = t & 63;
        float o = 0.f;
        for (int c = 0; c < CC; c++) o = fmaf(sw[r][c], vis[c][wc], o);
        out[b * RR * CWN + t] = o;
    }
}

// ============================================================================
extern "C" void kernel_launch(void* const* d_in, const int* in_sizes, int n_in,
                              void* d_out, int out_size) {
    const float* xi       = (const float*)d_in[0];
    const float* memory   = (const float*)d_in[1];
    const float* vism     = (const float*)d_in[2];
    const float* linkm    = (const float*)d_in[3];
    const float* rlinkm   = (const float*)d_in[4];
    const float* prec     = (const float*)d_in[5];
    const float* rw       = (const float*)d_in[6];
    const float* ww       = (const float*)d_in[7];
    const float* usage    = (const float*)d_in[8];
    // d_in[9] = least_used_mem (unused; recomputed exactly)
    const int*   rp       = (const int*)d_in[10];
    const float* W_rq     = (const float*)d_in[11];
    const float* b_rq     = (const float*)d_in[12];
    const float* W_wv     = (const float*)d_in[13];
    const float* b_wv     = (const float*)d_in[14];
    const float* W_ig     = (const float*)d_in[15];
    const float* b_ig     = (const float*)d_in[16];
    const float* W_wg     = (const float*)d_in[17];
    const float* b_wg     = (const float*)d_in[18];
    float* out = (float*)d_out;

    k1_setup<<<BB, 256>>>(xi, vism, linkm, rlinkm, prec, rw, ww, usage, rp,
                          W_rq, b_rq, W_wv, b_wv, W_ig, b_ig, W_wg, b_wg);
    k2_scan<<<BB * NBLK + UMB, 256>>>(memory, usage, rp);
    k3_finish<<<BB, 256>>>(memory, rp, out);
}

// round 3
// speedup vs baseline: 1.2242x; 1.2242x over previous
#include <cuda_runtime.h>
#include <float.h>
#include <math.h>

#define BB 8
#define DD 256
#define MEMN 131072
#define CWN 64
#define RR 4
#define KK 4
#define TKL 8
#define CC 25
#define DELTA_F 0.005f
#define EPS_F 1e-6f

#define NBLK 64
#define ROWS_PER_BLK (MEMN / NBLK)   // 2048
#define UMB 16
#define UMCH (MEMN / UMB)            // 8192

// ---------------- device scratch (no allocations allowed) ----------------
__device__ float g_q[BB][DD];                 // raw read_query
__device__ float g_visnew[BB][CC][CWN];       // updated visible_memory rows
__device__ float g_relnew[BB][CC];            // updated usage at read positions
__device__ int   g_fp[BB][KK];
__device__ int   g_bp[BB][KK];
__device__ float g_bv[BB][RR][NBLK][KK];      // per-block top-4 values
__device__ int   g_bi[BB][RR][NBLK][KK];      // per-block top-4 indices
__device__ float g_uv[UMB];                   // usage argmin partials (batch 0)
__device__ int   g_ui[UMB];

// ---------------- helpers ----------------
__device__ __forceinline__ float d4(float4 a, float4 b, float acc) {
    acc = fmaf(a.x, b.x, acc);
    acc = fmaf(a.y, b.y, acc);
    acc = fmaf(a.z, b.z, acc);
    acc = fmaf(a.w, b.w, acc);
    return acc;
}

// top-4 insertion; larger value wins, ties -> lower index (jax.lax.top_k)
__device__ __forceinline__ void ins4s(float s, int m,
    float &v0, int &i0, float &v1, int &i1,
    float &v2, int &i2, float &v3, int &i3)
{
    if (!((s > v3) || (s == v3 && m < i3))) return;
    v3 = s; i3 = m;
    if ((v3 > v2) || (v3 == v2 && i3 < i2)) { float tv=v2; int ti=i2; v2=v3; i2=i3; v3=tv; i3=ti; }
    if ((v2 > v1) || (v2 == v1 && i2 < i1)) { float tv=v1; int ti=i1; v1=v2; i1=i2; v2=tv; i2=ti; }
    if ((v1 > v0) || (v1 == v0 && i1 < i0)) { float tv=v0; int ti=i0; v0=v1; i0=i1; v1=tv; i1=ti; }
}

__device__ __forceinline__ float sig_(float x) { return 1.f / (1.f + expf(-x)); }

// ============================================================================
// K1: projections (parallel thread ranges) + small state updates +
//     link diagonals (8-way parallel) + fp/bp. 1 block/batch, 512 threads.
// ============================================================================
__global__ void __launch_bounds__(512) k1_setup(
    const float* __restrict__ xi,
    const float* __restrict__ visible_memory,
    const float* __restrict__ link_matrix,
    const float* __restrict__ rev_link_matrix,
    const float* __restrict__ precedence,
    const float* __restrict__ read_weights,
    const float* __restrict__ write_weights,
    const float* __restrict__ usage,
    const int*   __restrict__ read_positions,
    const float* __restrict__ W_rq, const float* __restrict__ b_rq,
    const float* __restrict__ W_wv, const float* __restrict__ b_wv,
    const float* __restrict__ W_ig, const float* __restrict__ b_ig,
    const float* __restrict__ W_wg, const float* __restrict__ b_wg)
{
    int b = blockIdx.x;
    int t = threadIdx.x;

    __shared__ float xs[DD];
    __shared__ float wv_s[CWN];
    __shared__ float ig_s[CC];
    __shared__ float wg_s;
    __shared__ int   rp_s[CC];
    __shared__ float rw_s[CC], rel_s[CC], u_s[CC], imin_s[CC], wwnew_s[CC];
    __shared__ float minrel_s;
    __shared__ float fw_s[TKL], bw_s[TKL];

    if (t < DD) xs[t] = xi[b * DD + t];
    if (t < CC) rp_s[t] = read_positions[b * CC + t];
    __syncthreads();

    // ---- all projections in parallel on disjoint thread ranges ----
    if (t < DD) {
        float acc = b_rq[t];
        #pragma unroll 8
        for (int d = 0; d < DD; d++) acc = fmaf(xs[d], W_rq[d * 256 + t], acc);
        g_q[b][t] = acc;
    } else if (t < DD + CWN) {
        int o = t - DD;
        float acc = b_wv[o];
        #pragma unroll 8
        for (int d = 0; d < DD; d++) acc = fmaf(xs[d], W_wv[d * CWN + o], acc);
        wv_s[o] = acc;
    } else if (t < DD + CWN + CC) {
        int o = t - DD - CWN;
        float acc = b_ig[o];
        #pragma unroll 8
        for (int d = 0; d < DD; d++) acc = fmaf(xs[d], W_ig[d * CC + o], acc);
        ig_s[o] = sig_(acc);
    } else if (t == DD + CWN + CC) {
        float acc = b_wg[0];
        #pragma unroll 8
        for (int d = 0; d < DD; d++) acc = fmaf(xs[d], W_wg[d], acc);
        wg_s = sig_(acc);
    }

    // ---- gather small state (independent of projections) ----
    if (t >= 384 && t < 384 + CC) {
        int c = t - 384;
        int p = rp_s[c];
        float rw  = __ldg(&read_weights [(size_t)b * MEMN + p]);
        float ww  = __ldg(&write_weights[(size_t)b * MEMN + p]);
        float rel = __ldg(&usage        [(size_t)b * MEMN + p]);
        rw_s[c]  = rw;
        rel_s[c] = rel;
        u_s[c]   = (rw + ww > DELTA_F) ? 1.f : 0.f;
    }
    __syncthreads();

    if (t == 0) {
        float mn = rel_s[0];
        for (int c = 1; c < CC; c++) mn = fminf(mn, rel_s[c]);
        minrel_s = mn;
    }
    __syncthreads();
    if (t < CC) {
        float Imin = (rel_s[t] == minrel_s) ? 1.f : 0.f;
        imin_s[t] = Imin;
        float u = u_s[t], rel = rel_s[t];
        g_relnew[b][t] = (1.f - rel) * u + rel * (1.f - u);   // TIMESTEP = 1
        wwnew_s[t] = wg_s * (ig_s[t] * rw_s[t] + (1.f - ig_s[t]) * Imin);
    }
    __syncthreads();

    // updated visible_memory rows
    for (int e = t; e < CC * CWN; e += blockDim.x) {
        int c = e / CWN, k = e % CWN;
        float v = visible_memory[((size_t)b * CC + c) * CWN + k];
        g_visnew[b][c][k] = v * (1.f - imin_s[c]) + wwnew_s[c] * wv_s[k];
    }

    // ---- link / rev-link diagonals: 8-way parallel ----
    if (t < TKL) {
        int m = t;
        // updated write_weights at index m (scatter, last writer wins)
        float wwf = __ldg(&write_weights[(size_t)b * MEMN + m]);
        for (int c = 0; c < CC; c++) if (rp_s[c] == m) wwf = wwnew_s[c];
        // tww[m] = updated write_weights at trp[m] = rp[16+m]
        int tp = rp_s[RR * KK + m];
        float tw = __ldg(&write_weights[(size_t)b * MEMN + tp]);
        for (int c = 0; c < CC; c++) if (rp_s[c] == tp) tw = wwnew_s[c];
        // prec_dense[m] : precedence scattered at trp, read at m (last j wins)
        float pd = 0.f;
        for (int j = 0; j < TKL; j++)
            if (rp_s[RR * KK + j] == m) pd = __ldg(&precedence[b * TKL + j]);
        float trw = __ldg(&read_weights[(size_t)b * MEMN + tp]);
        float Ld = (1.f - wwf) * __ldg(&link_matrix    [((size_t)b * MEMN + m) * TKL + m])
                 + wwf * __ldg(&precedence[b * TKL + m]);
        float Rd = (1.f - tw ) * __ldg(&rev_link_matrix[((size_t)b * MEMN + m) * TKL + m])
                 + tw  * pd;
        fw_s[m] = Ld * trw;
        bw_s[m] = Rd * trw;
    }
    __syncthreads();

    if (t == 0) {
        bool used[TKL];
        for (int m = 0; m < TKL; m++) used[m] = false;
        for (int k = 0; k < KK; k++) {
            int best = -1;
            for (int m = 0; m < TKL; m++)
                if (!used[m] && (best < 0 || fw_s[m] > fw_s[best])) best = m;
            used[best] = true;
            g_fp[b][k] = best;
        }
        for (int m = 0; m < TKL; m++) used[m] = false;
        for (int k = 0; k < KK; k++) {
            int best = -1;
            for (int m = 0; m < TKL; m++)
                if (!used[m] && (best < 0 || bw_s[m] > bw_s[best])) best = m;
            used[best] = true;
            g_bp[b][k] = best;
        }
    }
}

// ============================================================================
// K2: full-memory score scan (coalesced, 8 lanes/row) + per-block top-4.
//     Extra UMB blocks: masked usage argmin for batch 0.
// ============================================================================
__global__ void __launch_bounds__(256) k2_scan(
    const float* __restrict__ memv,
    const float* __restrict__ usage,
    const int*   __restrict__ rp)
{
    int t = threadIdx.x;

    if (blockIdx.x >= BB * NBLK) {
        // ---- usage argmin for batch 0 (read positions masked out) ----
        int ib = blockIdx.x - BB * NBLK;
        __shared__ int   rp0[CC];
        __shared__ float svv[256];
        __shared__ int   sii[256];
        if (t < CC) rp0[t] = rp[t];
        __syncthreads();
        float bv = FLT_MAX; int bi = 0x7fffffff;
        int base = ib * UMCH;
        for (int j = t; j < UMCH; j += 256) {
            int idx = base + j;
            float v = usage[idx];
            bool masked = false;
            #pragma unroll
            for (int c = 0; c < CC; c++) masked |= (rp0[c] == idx);
            if (!masked && (v < bv || (v == bv && idx < bi))) { bv = v; bi = idx; }
        }
        svv[t] = bv; sii[t] = bi;
        __syncthreads();
        for (int s = 128; s > 0; s >>= 1) {
            if (t < s) {
                if (svv[t+s] < svv[t] || (svv[t+s] == svv[t] && sii[t+s] < sii[t])) {
                    svv[t] = svv[t+s]; sii[t] = sii[t+s];
                }
            }
            __syncthreads();
        }
        if (t == 0) { g_uv[ib] = svv[0]; g_ui[ib] = sii[0]; }
        return;
    }

    int b   = blockIdx.x / NBLK;
    int blk = blockIdx.x % NBLK;
    int rowbase = blk * ROWS_PER_BLK;
    int lane = t & 31, w = t >> 5;
    int sub = lane & 7, grp = lane >> 3;

    __shared__ int ns;
    __shared__ int srow[CC];
    __shared__ float msv[RR][128];
    __shared__ int   msi[RR][128];
    if (t == 0) ns = 0;
    __syncthreads();
    if (t < CC) {
        int p = rp[b * CC + t];
        if (p >= rowbase && p < rowbase + ROWS_PER_BLK) { int k = atomicAdd(&ns, 1); srow[k] = p; }
    }

    // query columns for this lane: cols sub*4..+3 and 32+sub*4..+3, all 4 queries
    float4 q0[RR], q1[RR];
    #pragma unroll
    for (int r = 0; r < RR; r++) {
        q0[r] = *(const float4*)&g_q[b][r * CWN + sub * 4];
        q1[r] = *(const float4*)&g_q[b][r * CWN + 32 + sub * 4];
    }
    __syncthreads();
    int nspec = ns;

    float tv0 = -FLT_MAX, tv1 = -FLT_MAX, tv2 = -FLT_MAX, tv3 = -FLT_MAX;
    int   ti0 = 0x7fffffff, ti1 = 0x7fffffff, ti2 = 0x7fffffff, ti3 = 0x7fffffff;

    const float4* basep = (const float4*)(memv + (size_t)b * MEMN * CWN);
    #pragma unroll 2
    for (int it = 0; it < ROWS_PER_BLK / 32; it++) {
        int row = rowbase + it * 32 + w * 4 + grp;
        const float4* p = basep + (size_t)row * 16;
        float4 a0 = __ldcs(p + sub);
        float4 a1 = __ldcs(p + 8 + sub);

        float sq = d4(a0, a0, 0.f); sq = d4(a1, a1, sq);
        float dt0 = d4(a0, q0[0], 0.f); dt0 = d4(a1, q1[0], dt0);
        float dt1 = d4(a0, q0[1], 0.f); dt1 = d4(a1, q1[1], dt1);
        float dt2 = d4(a0, q0[2], 0.f); dt2 = d4(a1, q1[2], dt2);
        float dt3 = d4(a0, q0[3], 0.f); dt3 = d4(a1, q1[3], dt3);

        #pragma unroll
        for (int m = 4; m >= 1; m >>= 1) {
            sq  += __shfl_xor_sync(0xffffffffu, sq,  m);
            dt0 += __shfl_xor_sync(0xffffffffu, dt0, m);
            dt1 += __shfl_xor_sync(0xffffffffu, dt1, m);
            dt2 += __shfl_xor_sync(0xffffffffu, dt2, m);
            dt3 += __shfl_xor_sync(0xffffffffu, dt3, m);
        }

        if (sub < RR) {
            float myd = (sub == 0) ? dt0 : (sub == 1) ? dt1 : (sub == 2) ? dt2 : dt3;
            float s = 2.f * myd - sq;
            for (int j = 0; j < nspec; j++) if (srow[j] == row) s = -FLT_MAX;
            ins4s(s, row, tv0, ti0, tv1, ti1, tv2, ti2, tv3, ti3);
        }
    }

    if (sub < RR) {
        int slot = w * 16 + grp * 4;
        msv[sub][slot + 0] = tv0; msi[sub][slot + 0] = ti0;
        msv[sub][slot + 1] = tv1; msi[sub][slot + 1] = ti1;
        msv[sub][slot + 2] = tv2; msi[sub][slot + 2] = ti2;
        msv[sub][slot + 3] = tv3; msi[sub][slot + 3] = ti3;
    }
    __syncthreads();

    if (t < RR) {
        float v0 = -FLT_MAX, v1 = -FLT_MAX, v2 = -FLT_MAX, v3 = -FLT_MAX;
        int   i0 = 0x7fffffff, i1 = 0x7fffffff, i2 = 0x7fffffff, i3 = 0x7fffffff;
        for (int j = 0; j < 128; j++)
            ins4s(msv[t][j], msi[t][j], v0, i0, v1, i1, v2, i2, v3, i3);
        g_bv[b][t][blk][0] = v0; g_bi[b][t][blk][0] = i0;
        g_bv[b][t][blk][1] = v1; g_bi[b][t][blk][1] = i1;
        g_bv[b][t][blk][2] = v2; g_bi[b][t][blk][2] = i2;
        g_bv[b][t][blk][3] = v3; g_bi[b][t][blk][3] = i3;
    }
}

// ============================================================================
// K3: global merge + fp/bp/lum + clip + gather(with substitution) + cosine
//     softmax read. 1 block/batch.
// ============================================================================
__global__ void __launch_bounds__(256) k3_finish(
    const float* __restrict__ memv,
    const int*   __restrict__ rp,
    float* __restrict__ out)
{
    int b = blockIdx.x;
    int t = threadIdx.x;

    __shared__ float q[RR][CWN];
    __shared__ float kq[RR][CWN];
    __shared__ float qn[RR];
    __shared__ int   rps[CC];
    __shared__ int   valid[CC];
    __shared__ float specs[RR][CC];
    __shared__ float cv[RR][NBLK * KK];
    __shared__ int   ci[RR][NBLK * KK];
    __shared__ int   pos[CC];
    __shared__ int   maxlen_s;
    __shared__ int   rowsrc[CC];
    __shared__ float vis[CC][CWN];
    __shared__ float vinv[CC];
    __shared__ float sim[RR][CC];
    __shared__ float sw[RR][CC];

    // 1. load q
    q[t >> 6][t & 63] = g_q[b][t];
    __syncthreads();

    // 2. q norms, read positions, stage block candidates
    if (t < RR) {
        float s = 0.f;
        for (int wc = 0; wc < CWN; wc++) s = fmaf(q[t][wc], q[t][wc], s);
        qn[t] = 1.f / (sqrtf(s) + EPS_F);
    }
    if (t >= 32 && t < 32 + CC) rps[t - 32] = rp[b * CC + (t - 32)];
    for (int e = t; e < RR * NBLK * KK; e += 256) {
        int r = e / (NBLK * KK), j = e % (NBLK * KK);
        cv[r][j] = (&g_bv[b][r][0][0])[j];
        ci[r][j] = (&g_bi[b][r][0][0])[j];
    }
    __syncthreads();

    // 3. kq, validity (last occurrence), special-row scores, max_length
    kq[t >> 6][t & 63] = q[t >> 6][t & 63] * qn[t >> 6];
    if (t < CC) {
        int v = 1;
        for (int c = t + 1; c < CC; c++) if (rps[c] == rps[t]) v = 0;
        valid[t] = v;
    }
    if (t >= 128 && t < 128 + RR * CC) {
        int e = t - 128;
        int c = e / RR, r = e % RR;
        float dt = 0.f, sq = 0.f;
        for (int wc = 0; wc < CWN; wc++) {
            float m = g_visnew[b][c][wc];
            dt = fmaf(q[r][wc], m, dt);
            sq = fmaf(m, m, sq);
        }
        specs[r][c] = 2.f * dt - sq;
    }
    if (t == 255) {
        float bv = FLT_MAX; int bi = 0x7fffffff;
        for (int i = 0; i < UMB; i++) {
            float v = g_uv[i]; int ix = g_ui[i];
            if (v < bv || (v == bv && ix < bi)) { bv = v; bi = ix; }
        }
        for (int c = 0; c < CC; c++) {
            int p0 = rp[c];                 // batch 0
            int last = 1;
            for (int c2 = c + 1; c2 < CC; c2++) if (rp[c2] == p0) last = 0;
            if (!last) continue;
            float v = g_relnew[0][c];
            if (v < bv || (v == bv && p0 < bi)) { bv = v; bi = p0; }
        }
        maxlen_s = bi;
    }
    __syncthreads();

    // 4. global top-4 per r; assemble positions
    if (t < RR) {
        float v0 = -FLT_MAX, v1 = -FLT_MAX, v2 = -FLT_MAX, v3 = -FLT_MAX;
        int   i0 = 0x7fffffff, i1 = 0x7fffffff, i2 = 0x7fffffff, i3 = 0x7fffffff;
        for (int j = 0; j < NBLK * KK; j++)
            ins4s(cv[t][j], ci[t][j], v0, i0, v1, i1, v2, i2, v3, i3);
        for (int c = 0; c < CC; c++)
            if (valid[c]) ins4s(specs[t][c], rps[c], v0, i0, v1, i1, v2, i2, v3, i3);
        pos[t * 4 + 0] = i0; pos[t * 4 + 1] = i1; pos[t * 4 + 2] = i2; pos[t * 4 + 3] = i3;
    }
    if (t == 4) {
        for (int k = 0; k < KK; k++) { pos[16 + k] = g_fp[b][k]; pos[20 + k] = g_bp[b][k]; }
        pos[24] = CC + 1;   // lum = C + 1 = 26
    }
    __syncthreads();

    // 5. clip + row source (substitute updated rows; last occurrence wins)
    if (t < CC) {
        int p = pos[t];
        int ml = maxlen_s;
        p = p < 0 ? 0 : (p > ml ? ml : p);
        pos[t] = p;
        int s = -1;
        for (int c = 0; c < CC; c++) if (rps[c] == p) s = c;
        rowsrc[t] = s;
    }
    __syncthreads();

    // 6. gather visible rows
    for (int e = t; e < CC * CWN; e += 256) {
        int c = e / CWN, wc = e % CWN;
        int s = rowsrc[c];
        vis[c][wc] = (s >= 0) ? g_visnew[b][s][wc]
                              : memv[((size_t)b * MEMN + pos[c]) * CWN + wc];
    }
    __syncthreads();

    // 7. visible norms
    if (t < CC) {
        float s = 0.f;
        for (int wc = 0; wc < CWN; wc++) s = fmaf(vis[t][wc], vis[t][wc], s);
        vinv[t] = 1.f / (sqrtf(s) + EPS_F);
    }
    __syncthreads();

    // 8. cosine similarities
    if (t < RR * CC) {
        int r = t / CC, c = t % CC;
        float s = 0.f;
        for (int wc = 0; wc < CWN; wc++) s = fmaf(kq[r][wc], vis[c][wc], s);
        sim[r][c] = s * vinv[c];
    }
    __syncthreads();

    // 9. softmax over candidates
    if (t < RR) {
        float mx = -FLT_MAX;
        for (int c = 0; c < CC; c++) mx = fmaxf(mx, sim[t][c]);
        float sum = 0.f;
        for (int c = 0; c < CC; c++) { float e = expf(sim[t][c] - mx); sw[t][c] = e; sum += e; }
        float inv = 1.f / sum;
        for (int c = 0; c < CC; c++) sw[t][c] *= inv;
    }
    __syncthreads();

    // 10. read vectors
    {
        int r = t >> 6, wc = t & 63;
        float o = 0.f;
        for (int c = 0; c < CC; c++) o = fmaf(sw[r][c], vis[c][wc], o);
        out[b * RR * CWN + t] = o;
    }
}

// ============================================================================
extern "C" void kernel_launch(void* const* d_in, const int* in_sizes, int n_in,
                              void* d_out, int out_size) {
    const float* xi       = (const float*)d_in[0];
    const float* memory   = (const float*)d_in[1];
    const float* vism     = (const float*)d_in[2];
    const float* linkm    = (const float*)d_in[3];
    const float* rlinkm   = (const float*)d_in[4];
    const float* prec     = (const float*)d_in[5];
    const float* rw       = (const float*)d_in[6];
    const float* ww       = (const float*)d_in[7];
    const float* usage    = (const float*)d_in[8];
    // d_in[9] = least_used_mem (unused; recomputed exactly)
    const int*   rp       = (const int*)d_in[10];
    const float* W_rq     = (const float*)d_in[11];
    const float* b_rq     = (const float*)d_in[12];
    const float* W_wv     = (const float*)d_in[13];
    const float* b_wv     = (const float*)d_in[14];
    const float* W_ig     = (const float*)d_in[15];
    const float* b_ig     = (const float*)d_in[16];
    const float* W_wg     = (const float*)d_in[17];
    const float* b_wg     = (const float*)d_in[18];
    float* out = (float*)d_out;

    k1_setup<<<BB, 512>>>(xi, vism, linkm, rlinkm, prec, rw, ww, usage, rp,
                          W_rq, b_rq, W_wv, b_wv, W_ig, b_ig, W_wg, b_wg);
    k2_scan<<<BB * NBLK + UMB, 256>>>(memory, usage, rp);
    k3_finish<<<BB, 256>>>(memory, rp, out);
}

// round 4
// speedup vs baseline: 1.2811x; 1.0465x over previous
#include <cuda_runtime.h>
#include <float.h>
#include <math.h>

#define BB 8
#define DD 256
#define MEMN 131072
#define CWN 64
#define RR 4
#define KK 4
#define TKL 8
#define CC 25
#define DELTA_F 0.005f
#define EPS_F 1e-6f

#define NBLK 64
#define ROWS_PER_BLK (MEMN / NBLK)   // 2048
#define UMB 16
#define UMCH (MEMN / UMB)            // 8192

// ---------------- device scratch (no allocations allowed) ----------------
__device__ float g_q[BB][DD];                 // raw read_query
__device__ float g_visnew[BB][CC][CWN];       // updated visible_memory rows
__device__ float g_relnew[BB][CC];            // updated usage at read positions
__device__ int   g_fp[BB][KK];
__device__ int   g_bp[BB][KK];
__device__ float g_bv[BB][RR][NBLK][KK];      // per-block top-4 values
__device__ int   g_bi[BB][RR][NBLK][KK];      // per-block top-4 indices
__device__ float g_uv[UMB];                   // usage argmin partials (batch 0)
__device__ int   g_ui[UMB];

// ---------------- helpers ----------------
__device__ __forceinline__ float d4(float4 a, float4 b, float acc) {
    acc = fmaf(a.x, b.x, acc);
    acc = fmaf(a.y, b.y, acc);
    acc = fmaf(a.z, b.z, acc);
    acc = fmaf(a.w, b.w, acc);
    return acc;
}

// top-4 insertion; larger value wins, ties -> lower index (jax.lax.top_k)
__device__ __forceinline__ void ins4s(float s, int m,
    float &v0, int &i0, float &v1, int &i1,
    float &v2, int &i2, float &v3, int &i3)
{
    if (!((s > v3) || (s == v3 && m < i3))) return;
    v3 = s; i3 = m;
    if ((v3 > v2) || (v3 == v2 && i3 < i2)) { float tv=v2; int ti=i2; v2=v3; i2=i3; v3=tv; i3=ti; }
    if ((v2 > v1) || (v2 == v1 && i2 < i1)) { float tv=v1; int ti=i1; v1=v2; i1=i2; v2=tv; i2=ti; }
    if ((v1 > v0) || (v1 == v0 && i1 < i0)) { float tv=v0; int ti=i0; v0=v1; i0=i1; v1=tv; i1=ti; }
}

__device__ __forceinline__ float sig_(float x) { return 1.f / (1.f + expf(-x)); }

// ============================================================================
// K1: latency-optimized projections (d-split partial sums) + state updates +
//     link diagonals + fp/bp. 1 block/batch, 1024 threads.
// ============================================================================
__global__ void __launch_bounds__(1024) k1_setup(
    const float* __restrict__ xi,
    const float* __restrict__ visible_memory,
    const float* __restrict__ link_matrix,
    const float* __restrict__ rev_link_matrix,
    const float* __restrict__ precedence,
    const float* __restrict__ read_weights,
    const float* __restrict__ write_weights,
    const float* __restrict__ usage,
    const int*   __restrict__ read_positions,
    const float* __restrict__ W_rq, const float* __restrict__ b_rq,
    const float* __restrict__ W_wv, const float* __restrict__ b_wv,
    const float* __restrict__ W_ig, const float* __restrict__ b_ig,
    const float* __restrict__ W_wg, const float* __restrict__ b_wg)
{
    int b = blockIdx.x;
    int t = threadIdx.x;

    __shared__ float xs[DD];
    __shared__ float prq[4][DD];      // rq partials: 4 d-chunks x 256 outputs
    __shared__ float pwv[16][CWN];    // wv partials: 16 d-chunks x 64 outputs
    __shared__ float pig[16][CC];     // ig partials
    __shared__ float pwg[DD];         // wg partials
    __shared__ float wv_s[CWN];
    __shared__ float ig_s[CC];
    __shared__ float wg_s;
    __shared__ int   rp_s[CC];
    __shared__ float rw_s[CC], rel_s[CC], u_s[CC], imin_s[CC], wwnew_s[CC];
    __shared__ float minrel_s;
    __shared__ float fw_s[TKL], bw_s[TKL];

    if (t < DD) xs[t] = xi[b * DD + t];
    if (t >= 512 && t < 512 + CC) rp_s[t - 512] = read_positions[b * CC + (t - 512)];
    __syncthreads();

    // ---- concurrent scattered state gather (threads 960+) ----
    if (t >= 960 && t < 960 + CC) {
        int c = t - 960;
        int p = rp_s[c];
        float rw  = __ldg(&read_weights [(size_t)b * MEMN + p]);
        float ww  = __ldg(&write_weights[(size_t)b * MEMN + p]);
        float rel = __ldg(&usage        [(size_t)b * MEMN + p]);
        rw_s[c]  = rw;
        rel_s[c] = rel;
        u_s[c]   = (rw + ww > DELTA_F) ? 1.f : 0.f;
    }

    // ---- Phase A: rq (4-way d split, 64 d each) ----
    {
        int o = t & 255, c = t >> 8;
        const float* W = W_rq + (size_t)(c * 64) * 256 + o;
        float a0 = 0.f, a1 = 0.f, a2 = 0.f, a3 = 0.f;
        #pragma unroll 4
        for (int d = 0; d < 64; d += 4) {
            a0 = fmaf(xs[c * 64 + d + 0], W[(d + 0) * 256], a0);
            a1 = fmaf(xs[c * 64 + d + 1], W[(d + 1) * 256], a1);
            a2 = fmaf(xs[c * 64 + d + 2], W[(d + 2) * 256], a2);
            a3 = fmaf(xs[c * 64 + d + 3], W[(d + 3) * 256], a3);
        }
        prq[c][o] = (a0 + a1) + (a2 + a3);
    }

    // ---- Phase B: wv (16-way d split, 16 d each) ----
    {
        int o = t & 63, c = t >> 6;
        const float* W = W_wv + (size_t)(c * 16) * CWN + o;
        float a0 = 0.f, a1 = 0.f;
        #pragma unroll
        for (int d = 0; d < 16; d += 2) {
            a0 = fmaf(xs[c * 16 + d + 0], W[(d + 0) * CWN], a0);
            a1 = fmaf(xs[c * 16 + d + 1], W[(d + 1) * CWN], a1);
        }
        pwv[c][o] = a0 + a1;
    }

    // ---- Phase C: ig (16-way d split on first 400 threads) ----
    if (t < 400) {
        int o = t % CC, c = t / CC;
        const float* W = W_ig + (size_t)(c * 16) * CC + o;
        float a0 = 0.f, a1 = 0.f;
        #pragma unroll
        for (int d = 0; d < 16; d += 2) {
            a0 = fmaf(xs[c * 16 + d + 0], W[(d + 0) * CC], a0);
            a1 = fmaf(xs[c * 16 + d + 1], W[(d + 1) * CC], a1);
        }
        pig[c][o] = a0 + a1;
    }

    // ---- Phase D: wg (256-way) ----
    if (t >= 512 && t < 768) {
        int d = t - 512;
        pwg[d] = xs[d] * __ldg(&W_wg[d]);
    }
    __syncthreads();

    // ---- combine partials ----
    if (t < DD) {
        g_q[b][t] = b_rq[t] + ((prq[0][t] + prq[1][t]) + (prq[2][t] + prq[3][t]));
    } else if (t < DD + CWN) {
        int o = t - DD;
        float s = b_wv[o];
        #pragma unroll
        for (int c = 0; c < 16; c++) s += pwv[c][o];
        wv_s[o] = s;
    } else if (t < DD + CWN + CC) {
        int o = t - DD - CWN;
        float s = b_ig[o];
        #pragma unroll
        for (int c = 0; c < 16; c++) s += pig[c][o];
        ig_s[o] = sig_(s);
    } else if (t == DD + CWN + CC) {
        float s = b_wg[0];
        for (int d = 0; d < DD; d++) s += pwg[d];
        wg_s = sig_(s);
    } else if (t == 512) {
        float mn = rel_s[0];
        for (int c = 1; c < CC; c++) mn = fminf(mn, rel_s[c]);
        minrel_s = mn;
    }
    __syncthreads();

    if (t < CC) {
        float Imin = (rel_s[t] == minrel_s) ? 1.f : 0.f;
        imin_s[t] = Imin;
        float u = u_s[t], rel = rel_s[t];
        g_relnew[b][t] = (1.f - rel) * u + rel * (1.f - u);   // TIMESTEP = 1
        wwnew_s[t] = wg_s * (ig_s[t] * rw_s[t] + (1.f - ig_s[t]) * Imin);
    }
    __syncthreads();

    // updated visible_memory rows
    for (int e = t; e < CC * CWN; e += blockDim.x) {
        int c = e / CWN, k = e % CWN;
        float v = visible_memory[((size_t)b * CC + c) * CWN + k];
        g_visnew[b][c][k] = v * (1.f - imin_s[c]) + wwnew_s[c] * wv_s[k];
    }

    // ---- link / rev-link diagonals: 8-way parallel ----
    if (t < TKL) {
        int m = t;
        float wwf = __ldg(&write_weights[(size_t)b * MEMN + m]);
        for (int c = 0; c < CC; c++) if (rp_s[c] == m) wwf = wwnew_s[c];
        int tp = rp_s[RR * KK + m];
        float tw = __ldg(&write_weights[(size_t)b * MEMN + tp]);
        for (int c = 0; c < CC; c++) if (rp_s[c] == tp) tw = wwnew_s[c];
        float pd = 0.f;
        for (int j = 0; j < TKL; j++)
            if (rp_s[RR * KK + j] == m) pd = __ldg(&precedence[b * TKL + j]);
        float trw = __ldg(&read_weights[(size_t)b * MEMN + tp]);
        float Ld = (1.f - wwf) * __ldg(&link_matrix    [((size_t)b * MEMN + m) * TKL + m])
                 + wwf * __ldg(&precedence[b * TKL + m]);
        float Rd = (1.f - tw ) * __ldg(&rev_link_matrix[((size_t)b * MEMN + m) * TKL + m])
                 + tw  * pd;
        fw_s[m] = Ld * trw;
        bw_s[m] = Rd * trw;
    }
    __syncthreads();

    if (t == 0) {
        bool used[TKL];
        for (int m = 0; m < TKL; m++) used[m] = false;
        for (int k = 0; k < KK; k++) {
            int best = -1;
            for (int m = 0; m < TKL; m++)
                if (!used[m] && (best < 0 || fw_s[m] > fw_s[best])) best = m;
            used[best] = true;
            g_fp[b][k] = best;
        }
        for (int m = 0; m < TKL; m++) used[m] = false;
        for (int k = 0; k < KK; k++) {
            int best = -1;
            for (int m = 0; m < TKL; m++)
                if (!used[m] && (best < 0 || bw_s[m] > bw_s[best])) best = m;
            used[best] = true;
            g_bp[b][k] = best;
        }
    }
}

// ============================================================================
// K2: full-memory score scan (coalesced, 8 lanes/row) + per-block top-4.
//     Extra UMB blocks: masked usage argmin for batch 0.
//     min 4 blocks/SM -> single wave for 536 blocks.
// ============================================================================
__global__ void __launch_bounds__(256, 4) k2_scan(
    const float* __restrict__ memv,
    const float* __restrict__ usage,
    const int*   __restrict__ rp)
{
    int t = threadIdx.x;

    if (blockIdx.x >= BB * NBLK) {
        // ---- usage argmin for batch 0 (read positions masked out) ----
        int ib = blockIdx.x - BB * NBLK;
        __shared__ int   rp0[CC];
        __shared__ float svv[256];
        __shared__ int   sii[256];
        if (t < CC) rp0[t] = rp[t];
        __syncthreads();
        float bv = FLT_MAX; int bi = 0x7fffffff;
        int base = ib * UMCH;
        for (int j = t; j < UMCH; j += 256) {
            int idx = base + j;
            float v = usage[idx];
            bool masked = false;
            #pragma unroll
            for (int c = 0; c < CC; c++) masked |= (rp0[c] == idx);
            if (!masked && (v < bv || (v == bv && idx < bi))) { bv = v; bi = idx; }
        }
        svv[t] = bv; sii[t] = bi;
        __syncthreads();
        for (int s = 128; s > 0; s >>= 1) {
            if (t < s) {
                if (svv[t+s] < svv[t] || (svv[t+s] == svv[t] && sii[t+s] < sii[t])) {
                    svv[t] = svv[t+s]; sii[t] = sii[t+s];
                }
            }
            __syncthreads();
        }
        if (t == 0) { g_uv[ib] = svv[0]; g_ui[ib] = sii[0]; }
        return;
    }

    int b   = blockIdx.x / NBLK;
    int blk = blockIdx.x % NBLK;
    int rowbase = blk * ROWS_PER_BLK;
    int lane = t & 31, w = t >> 5;
    int sub = lane & 7, grp = lane >> 3;

    __shared__ int ns;
    __shared__ int srow[CC];
    __shared__ float msv[RR][128];
    __shared__ int   msi[RR][128];
    if (t == 0) ns = 0;
    __syncthreads();
    if (t < CC) {
        int p = rp[b * CC + t];
        if (p >= rowbase && p < rowbase + ROWS_PER_BLK) { int k = atomicAdd(&ns, 1); srow[k] = p; }
    }

    // query columns for this lane: cols sub*4..+3 and 32+sub*4..+3, all 4 queries
    float4 q0[RR], q1[RR];
    #pragma unroll
    for (int r = 0; r < RR; r++) {
        q0[r] = *(const float4*)&g_q[b][r * CWN + sub * 4];
        q1[r] = *(const float4*)&g_q[b][r * CWN + 32 + sub * 4];
    }
    __syncthreads();
    int nspec = ns;

    float tv0 = -FLT_MAX, tv1 = -FLT_MAX, tv2 = -FLT_MAX, tv3 = -FLT_MAX;
    int   ti0 = 0x7fffffff, ti1 = 0x7fffffff, ti2 = 0x7fffffff, ti3 = 0x7fffffff;

    const float4* basep = (const float4*)(memv + (size_t)b * MEMN * CWN);
    #pragma unroll 4
    for (int it = 0; it < ROWS_PER_BLK / 32; it++) {
        int row = rowbase + it * 32 + w * 4 + grp;
        const float4* p = basep + (size_t)row * 16;
        float4 a0 = __ldcs(p + sub);
        float4 a1 = __ldcs(p + 8 + sub);

        float sq = d4(a0, a0, 0.f); sq = d4(a1, a1, sq);
        float dt0 = d4(a0, q0[0], 0.f); dt0 = d4(a1, q1[0], dt0);
        float dt1 = d4(a0, q0[1], 0.f); dt1 = d4(a1, q1[1], dt1);
        float dt2 = d4(a0, q0[2], 0.f); dt2 = d4(a1, q1[2], dt2);
        float dt3 = d4(a0, q0[3], 0.f); dt3 = d4(a1, q1[3], dt3);

        #pragma unroll
        for (int m = 4; m >= 1; m >>= 1) {
            sq  += __shfl_xor_sync(0xffffffffu, sq,  m);
            dt0 += __shfl_xor_sync(0xffffffffu, dt0, m);
            dt1 += __shfl_xor_sync(0xffffffffu, dt1, m);
            dt2 += __shfl_xor_sync(0xffffffffu, dt2, m);
            dt3 += __shfl_xor_sync(0xffffffffu, dt3, m);
        }

        if (sub < RR) {
            float myd = (sub == 0) ? dt0 : (sub == 1) ? dt1 : (sub == 2) ? dt2 : dt3;
            float s = 2.f * myd - sq;
            for (int j = 0; j < nspec; j++) if (srow[j] == row) s = -FLT_MAX;
            ins4s(s, row, tv0, ti0, tv1, ti1, tv2, ti2, tv3, ti3);
        }
    }

    if (sub < RR) {
        int slot = w * 16 + grp * 4;
        msv[sub][slot + 0] = tv0; msi[sub][slot + 0] = ti0;
        msv[sub][slot + 1] = tv1; msi[sub][slot + 1] = ti1;
        msv[sub][slot + 2] = tv2; msi[sub][slot + 2] = ti2;
        msv[sub][slot + 3] = tv3; msi[sub][slot + 3] = ti3;
    }
    __syncthreads();

    if (t < RR) {
        float v0 = -FLT_MAX, v1 = -FLT_MAX, v2 = -FLT_MAX, v3 = -FLT_MAX;
        int   i0 = 0x7fffffff, i1 = 0x7fffffff, i2 = 0x7fffffff, i3 = 0x7fffffff;
        for (int j = 0; j < 128; j++)
            ins4s(msv[t][j], msi[t][j], v0, i0, v1, i1, v2, i2, v3, i3);
        g_bv[b][t][blk][0] = v0; g_bi[b][t][blk][0] = i0;
        g_bv[b][t][blk][1] = v1; g_bi[b][t][blk][1] = i1;
        g_bv[b][t][blk][2] = v2; g_bi[b][t][blk][2] = i2;
        g_bv[b][t][blk][3] = v3; g_bi[b][t][blk][3] = i3;
    }
}

// ============================================================================
// K3: global merge + fp/bp/lum + clip + gather(with substitution) + cosine
//     softmax read. 1 block/batch.
// ============================================================================
__global__ void __launch_bounds__(256) k3_finish(
    const float* __restrict__ memv,
    const int*   __restrict__ rp,
    float* __restrict__ out)
{
    int b = blockIdx.x;
    int t = threadIdx.x;

    __shared__ float q[RR][CWN];
    __shared__ float kq[RR][CWN];
    __shared__ float qn[RR];
    __shared__ int   rps[CC];
    __shared__ int   valid[CC];
    __shared__ float specs[RR][CC];
    __shared__ float cv[RR][NBLK * KK];
    __shared__ int   ci[RR][NBLK * KK];
    __shared__ int   pos[CC];
    __shared__ int   maxlen_s;
    __shared__ int   rowsrc[CC];
    __shared__ float vis[CC][CWN];
    __shared__ float vinv[CC];
    __shared__ float sim[RR][CC];
    __shared__ float sw[RR][CC];

    // 1. load q
    q[t >> 6][t & 63] = g_q[b][t];
    __syncthreads();

    // 2. q norms, read positions, stage block candidates
    if (t < RR) {
        float s = 0.f;
        for (int wc = 0; wc < CWN; wc++) s = fmaf(q[t][wc], q[t][wc], s);
        qn[t] = 1.f / (sqrtf(s) + EPS_F);
    }
    if (t >= 32 && t < 32 + CC) rps[t - 32] = rp[b * CC + (t - 32)];
    for (int e = t; e < RR * NBLK * KK; e += 256) {
        int r = e / (NBLK * KK), j = e % (NBLK * KK);
        cv[r][j] = (&g_bv[b][r][0][0])[j];
        ci[r][j] = (&g_bi[b][r][0][0])[j];
    }
    __syncthreads();

    // 3. kq, validity (last occurrence), special-row scores, max_length
    kq[t >> 6][t & 63] = q[t >> 6][t & 63] * qn[t >> 6];
    if (t < CC) {
        int v = 1;
        for (int c = t + 1; c < CC; c++) if (rps[c] == rps[t]) v = 0;
        valid[t] = v;
    }
    if (t >= 128 && t < 128 + RR * CC) {
        int e = t - 128;
        int c = e / RR, r = e % RR;
        float dt = 0.f, sq = 0.f;
        for (int wc = 0; wc < CWN; wc++) {
            float m = g_visnew[b][c][wc];
            dt = fmaf(q[r][wc], m, dt);
            sq = fmaf(m, m, sq);
        }
        specs[r][c] = 2.f * dt - sq;
    }
    if (t == 255) {
        float bv = FLT_MAX; int bi = 0x7fffffff;
        for (int i = 0; i < UMB; i++) {
            float v = g_uv[i]; int ix = g_ui[i];
            if (v < bv || (v == bv && ix < bi)) { bv = v; bi = ix; }
        }
        for (int c = 0; c < CC; c++) {
            int p0 = rp[c];                 // batch 0
            int last = 1;
            for (int c2 = c + 1; c2 < CC; c2++) if (rp[c2] == p0) last = 0;
            if (!last) continue;
            float v = g_relnew[0][c];
            if (v < bv || (v == bv && p0 < bi)) { bv = v; bi = p0; }
        }
        maxlen_s = bi;
    }
    __syncthreads();

    // 4. global top-4 per r; assemble positions
    if (t < RR) {
        float v0 = -FLT_MAX, v1 = -FLT_MAX, v2 = -FLT_MAX, v3 = -FLT_MAX;
        int   i0 = 0x7fffffff, i1 = 0x7fffffff, i2 = 0x7fffffff, i3 = 0x7fffffff;
        for (int j = 0; j < NBLK * KK; j++)
            ins4s(cv[t][j], ci[t][j], v0, i0, v1, i1, v2, i2, v3, i3);
        for (int c = 0; c < CC; c++)
            if (valid[c]) ins4s(specs[t][c], rps[c], v0, i0, v1, i1, v2, i2, v3, i3);
        pos[t * 4 + 0] = i0; pos[t * 4 + 1] = i1; pos[t * 4 + 2] = i2; pos[t * 4 + 3] = i3;
    }
    if (t == 4) {
        for (int k = 0; k < KK; k++) { pos[16 + k] = g_fp[b][k]; pos[20 + k] = g_bp[b][k]; }
        pos[24] = CC + 1;   // lum = C + 1 = 26
    }
    __syncthreads();

    // 5. clip + row source (substitute updated rows; last occurrence wins)
    if (t < CC) {
        int p = pos[t];
        int ml = maxlen_s;
        p = p < 0 ? 0 : (p > ml ? ml : p);
        pos[t] = p;
        int s = -1;
        for (int c = 0; c < CC; c++) if (rps[c] == p) s = c;
        rowsrc[t] = s;
    }
    __syncthreads();

    // 6. gather visible rows
    for (int e = t; e < CC * CWN; e += 256) {
        int c = e / CWN, wc = e % CWN;
        int s = rowsrc[c];
        vis[c][wc] = (s >= 0) ? g_visnew[b][s][wc]
                              : memv[((size_t)b * MEMN + pos[c]) * CWN + wc];
    }
    __syncthreads();

    // 7. visible norms
    if (t < CC) {
        float s = 0.f;
        for (int wc = 0; wc < CWN; wc++) s = fmaf(vis[t][wc], vis[t][wc], s);
        vinv[t] = 1.f / (sqrtf(s) + EPS_F);
    }
    __syncthreads();

    // 8. cosine similarities
    if (t < RR * CC) {
        int r = t / CC, c = t % CC;
        float s = 0.f;
        for (int wc = 0; wc < CWN; wc++) s = fmaf(kq[r][wc], vis[c][wc], s);
        sim[r][c] = s * vinv[c];
    }
    __syncthreads();

    // 9. softmax over candidates
    if (t < RR) {
        float mx = -FLT_MAX;
        for (int c = 0; c < CC; c++) mx = fmaxf(mx, sim[t][c]);
        float sum = 0.f;
        for (int c = 0; c < CC; c++) { float e = expf(sim[t][c] - mx); sw[t][c] = e; sum += e; }
        float inv = 1.f / sum;
        for (int c = 0; c < CC; c++) sw[t][c] *= inv;
    }
    __syncthreads();

    // 10. read vectors
    {
        int r = t >> 6, wc = t & 63;
        float o = 0.f;
        for (int c = 0; c < CC; c++) o = fmaf(sw[r][c], vis[c][wc], o);
        out[b * RR * CWN + t] = o;
    }
}

// ============================================================================
extern "C" void kernel_launch(void* const* d_in, const int* in_sizes, int n_in,
                              void* d_out, int out_size) {
    const float* xi       = (const float*)d_in[0];
    const float* memory   = (const float*)d_in[1];
    const float* vism     = (const float*)d_in[2];
    const float* linkm    = (const float*)d_in[3];
    const float* rlinkm   = (const float*)d_in[4];
    const float* prec     = (const float*)d_in[5];
    const float* rw       = (const float*)d_in[6];
    const float* ww       = (const float*)d_in[7];
    const float* usage    = (const float*)d_in[8];
    // d_in[9] = least_used_mem (unused; recomputed exactly)
    const int*   rp       = (const int*)d_in[10];
    const float* W_rq     = (const float*)d_in[11];
    const float* b_rq     = (const float*)d_in[12];
    const float* W_wv     = (const float*)d_in[13];
    const float* b_wv     = (const float*)d_in[14];
    const float* W_ig     = (const float*)d_in[15];
    const float* b_ig     = (const float*)d_in[16];
    const float* W_wg     = (const float*)d_in[17];
    const float* b_wg     = (const float*)d_in[18];
    float* out = (float*)d_out;

    k1_setup<<<BB, 1024>>>(xi, vism, linkm, rlinkm, prec, rw, ww, usage, rp,
                           W_rq, b_rq, W_wv, b_wv, W_ig, b_ig, W_wg, b_wg);
    k2_scan<<<BB * NBLK + UMB, 256>>>(memory, usage, rp);
    k3_finish<<<BB, 256>>>(memory, rp, out);
}